// round 13
// baseline (speedup 1.0000x reference)
#include <cuda_runtime.h>
#include <cuda_fp16.h>
#include <math.h>

#define NN 50000
#define IN_DIM 256
#define HID 32
#define NCLS 40
#define NEDGE 1600000
#define NMID 30
#define ADJCAP (NEDGE + 16 * NN)   // rows padded to multiples of 8 (16-slack for safety)

// ---------------- device scratch (no allocations allowed) ----------------
__device__ int    g_degc[NN], g_degr[NN];
__device__ int    g_offc[NN + 1], g_offr[NN + 1];   // 8-aligned row starts
__device__ int    g_curc[NN], g_curr[NN];
__device__ __align__(16) unsigned short g_adjc16[ADJCAP];
__device__ __align__(16) unsigned short g_adjr16[ADJCAP];
__device__ float  g_dinv[NN], g_cntinv[NN];
__device__ float  g_x0[NN * HID];
__device__ float  g_A [NN * HID];    // final-layer input (written once)
__device__ __align__(16) float  g_G [NN * HID];   // (h @ W) * dinv — gathered fp32
__device__ __align__(16) float  g_Bf[NN * HID];   // LN(relu(gcn)) — node-local fp32
__device__ __align__(16) __half g_Bh[NN * HID];   // fp16 gather copy (score path)
__device__ float  g_S[NN];           // s[j]=Σ|B-hm|·w2  — scalar gathered fp32
__device__ float  g_T[NN];           // t[i]=Σ hm·h·w0   — node-local scalar
__device__ float  g_G40[NN * NCLS];  // final (h @ Wl) * dinv

__device__ __forceinline__ float warpsum(float v) {
    #pragma unroll
    for (int o = 16; o > 0; o >>= 1) v += __shfl_xor_sync(0xffffffffu, v, o);
    return v;
}

// ---------------- setup: degrees, scans, CSR ----------------
__global__ void zero_deg() {
    for (int i = blockIdx.x * blockDim.x + threadIdx.x; i < NN;
         i += gridDim.x * blockDim.x) {
        g_degc[i] = 0;
        g_degr[i] = 0;
    }
}

__global__ void hist_edges(const int* __restrict__ ei) {
    for (int e = blockIdx.x * blockDim.x + threadIdx.x; e < NEDGE;
         e += gridDim.x * blockDim.x) {
        atomicAdd(&g_degr[ei[e]], 1);          // row
        atomicAdd(&g_degc[ei[NEDGE + e]], 1);  // col
    }
}

// one block, 1024 threads: exclusive scan of (deg rounded up to 8)
__global__ void scan_two() {
    __shared__ int wsum[33];
    const int tid = threadIdx.x, lane = tid & 31, wid = tid >> 5;
    for (int arr = 0; arr < 2; arr++) {
        const int* src = arr ? g_degr : g_degc;
        int*       dst = arr ? g_offr : g_offc;
        int run = 0;
        for (int base = 0; base < NN; base += 1024) {
            int i = base + tid;
            int v = (i < NN) ? ((src[i] + 7) & ~7) : 0;  // pad rows to 8
            int inc = v;
            #pragma unroll
            for (int o = 1; o < 32; o <<= 1) {
                int t = __shfl_up_sync(0xffffffffu, inc, o);
                if (lane >= o) inc += t;
            }
            if (lane == 31) wsum[wid] = inc;
            __syncthreads();
            if (wid == 0) {
                int s = wsum[lane];
                int si = s;
                #pragma unroll
                for (int o = 1; o < 32; o <<= 1) {
                    int t = __shfl_up_sync(0xffffffffu, si, o);
                    if (lane >= o) si += t;
                }
                wsum[lane] = si - s;            // exclusive warp prefix
                if (lane == 31) wsum[32] = si;  // chunk total
            }
            __syncthreads();
            if (i < NN) dst[i] = run + wsum[wid] + inc - v;
            run += wsum[32];
            __syncthreads();
        }
        if (tid == 0) dst[NN] = run;
        __syncthreads();
    }
}

__global__ void node_init() {
    for (int i = blockIdx.x * blockDim.x + threadIdx.x; i < NN;
         i += gridDim.x * blockDim.x) {
        g_curc[i] = g_offc[i];
        g_curr[i] = g_offr[i];
        g_dinv[i] = rsqrtf((float)(g_degc[i] + 1));  // +1 self loop
        g_cntinv[i] = 1.0f / fmaxf((float)g_degr[i], 1.0f);
    }
}

__global__ void scatter_edges(const int* __restrict__ ei) {
    for (int e = blockIdx.x * blockDim.x + threadIdx.x; e < NEDGE;
         e += gridDim.x * blockDim.x) {
        int r = ei[e];
        int c = ei[NEDGE + e];
        int p = atomicAdd(&g_curc[c], 1);
        g_adjc16[p] = (unsigned short)r;  // CSR by col (gcn target), stores source row
        int q = atomicAdd(&g_curr[r], 1);
        g_adjr16[q] = (unsigned short)c;  // CSR by row (mean_agg target), stores source col
    }
}

// ---------------- first layer: x@W0*dinv -> G ; LN(relu(x@W_res)) -> x0 ----------------
__global__ void kfirst(const float* __restrict__ x, const float* __restrict__ W0,
                       const float* __restrict__ Wres, const float* __restrict__ rg,
                       const float* __restrict__ rb) {
    __shared__ float Wsm[IN_DIM * HID];  // 32 KB
    const int tid = threadIdx.x;
    const int lane = tid & 31;
    const int i = (blockIdx.x * blockDim.x + tid) >> 5;  // node (grid exact)

    for (int k = tid; k < IN_DIM * HID; k += blockDim.x) Wsm[k] = W0[k];

    float xr[8];
    #pragma unroll
    for (int j = 0; j < 8; j++) xr[j] = x[i * IN_DIM + j * 32 + lane];
    __syncthreads();

    float acc0 = 0.f;
    #pragma unroll
    for (int j = 0; j < 8; j++) {
        #pragma unroll
        for (int t = 0; t < 32; t++) {
            float xv = __shfl_sync(0xffffffffu, xr[j], t);
            acc0 = fmaf(xv, Wsm[(j * 32 + t) * HID + lane], acc0);
        }
    }
    __syncthreads();
    for (int k = tid; k < IN_DIM * HID; k += blockDim.x) Wsm[k] = Wres[k];
    __syncthreads();

    float acc1 = 0.f;
    #pragma unroll
    for (int j = 0; j < 8; j++) {
        #pragma unroll
        for (int t = 0; t < 32; t++) {
            float xv = __shfl_sync(0xffffffffu, xr[j], t);
            acc1 = fmaf(xv, Wsm[(j * 32 + t) * HID + lane], acc1);
        }
    }

    g_G[i * HID + lane] = acc0 * g_dinv[i];

    float r = fmaxf(acc1, 0.f);
    float m = warpsum(r) * (1.f / HID);
    float d = r - m;
    float var = warpsum(d * d) * (1.f / HID);
    g_x0[i * HID + lane] = d * rsqrtf(var + 1e-5f) * rg[lane] + rb[lane];
}

// ---------------- GCN aggregate + bias + relu + LN (quad-edge, pipelined) ----------------
__global__ void k2_gcn_ln(const float* __restrict__ b, const float* __restrict__ gam,
                          const float* __restrict__ bet) {
    const int lane = threadIdx.x & 31;
    const int sub = lane & 7;      // float4 feature group: features [4sub..4sub+3]
    const int quad = lane >> 3;    // which of 4 edges per instruction
    const int i = (blockIdx.x * blockDim.x + threadIdx.x) >> 5;
    if (i >= NN) return;
    const float4* G4 = (const float4*)g_G;
    const int s = g_offc[i];
    const int e = s + g_degc[i];
    const int pend = s + ((e - s) & ~7);
    int p = s;
    float4 a0 = {0.f, 0.f, 0.f, 0.f}, a1 = {0.f, 0.f, 0.f, 0.f};
    if (p < pend) {
        uint4 iw = *(const uint4*)&g_adjc16[p];          // 8 indices
        while (p < pend) {
            const int pn = p + 8;
            uint4 iwn = iw;
            if (pn < pend) iwn = *(const uint4*)&g_adjc16[pn];  // prefetch next
            unsigned wa = (quad >= 2) ? iw.y : iw.x;
            unsigned wb = (quad >= 2) ? iw.w : iw.z;
            int ja = (quad & 1) ? (int)(wa >> 16) : (int)(wa & 0xffffu);
            int jb = (quad & 1) ? (int)(wb >> 16) : (int)(wb & 0xffffu);
            float4 va = G4[ja * 8 + sub];
            float4 vb = G4[jb * 8 + sub];
            a0.x += va.x; a0.y += va.y; a0.z += va.z; a0.w += va.w;
            a1.x += vb.x; a1.y += vb.y; a1.z += vb.z; a1.w += vb.w;
            iw = iwn;
            p = pn;
        }
    }
    for (; p < e; p += 4) {        // remainder: 4 edges per step, guarded
        if (p + quad < e) {
            int j = (int)g_adjc16[p + quad];
            float4 v = G4[j * 8 + sub];
            a0.x += v.x; a0.y += v.y; a0.z += v.z; a0.w += v.w;
        }
    }
    float ax = a0.x + a1.x, ay = a0.y + a1.y, az = a0.z + a1.z, aw = a0.w + a1.w;
    ax += __shfl_xor_sync(0xffffffffu, ax, 8);  ax += __shfl_xor_sync(0xffffffffu, ax, 16);
    ay += __shfl_xor_sync(0xffffffffu, ay, 8);  ay += __shfl_xor_sync(0xffffffffu, ay, 16);
    az += __shfl_xor_sync(0xffffffffu, az, 8);  az += __shfl_xor_sync(0xffffffffu, az, 16);
    aw += __shfl_xor_sync(0xffffffffu, aw, 8);  aw += __shfl_xor_sync(0xffffffffu, aw, 16);
    float4 self = G4[i * 8 + sub];               // self loop
    ax += self.x; ay += self.y; az += self.z; aw += self.w;
    const float dv = g_dinv[i];
    float4 bb = ((const float4*)b)[sub];
    float v0 = fmaxf(fmaf(dv, ax, bb.x), 0.f);
    float v1 = fmaxf(fmaf(dv, ay, bb.y), 0.f);
    float v2 = fmaxf(fmaf(dv, az, bb.z), 0.f);
    float v3 = fmaxf(fmaf(dv, aw, bb.w), 0.f);
    // LN over 32 features; each feature appears in 4 quads -> x0.25
    float m = warpsum(v0 + v1 + v2 + v3) * (0.25f / HID);
    float d0 = v0 - m, d1 = v1 - m, d2 = v2 - m, d3 = v3 - m;
    float var = warpsum(d0 * d0 + d1 * d1 + d2 * d2 + d3 * d3) * (0.25f / HID);
    float rs = rsqrtf(var + 1e-5f);
    float4 gg = ((const float4*)gam)[sub];
    float4 be = ((const float4*)bet)[sub];
    float o0 = d0 * rs * gg.x + be.x;
    float o1 = d1 * rs * gg.y + be.y;
    float o2 = d2 * rs * gg.z + be.z;
    float o3 = d3 * rs * gg.w + be.w;
    if (quad == 0) {
        ((float4*)g_Bf)[i * 8 + sub] = make_float4(o0, o1, o2, o3);
        __half2 h01 = __floats2half2_rn(o0, o1);
        __half2 h23 = __floats2half2_rn(o2, o3);
        uint2 packed;
        packed.x = *(unsigned*)&h01;
        packed.y = *(unsigned*)&h23;
        ((uint2*)g_Bh)[i * 8 + sub] = packed;
    }
}

// ---------------- mean_agg(B)->hm ; scalars S,T (quad-edge fp16, 16-wide pipelined) ----------------
__global__ void k3_mean(const float* __restrict__ w_ws) {
    const int lane = threadIdx.x & 31;
    const int sub = lane & 7;      // 4-half group: features [4sub..4sub+3]
    const int quad = lane >> 3;
    const int i = (blockIdx.x * blockDim.x + threadIdx.x) >> 5;
    if (i >= NN) return;
    const uint2* B4 = (const uint2*)g_Bh;   // 8B = 4 halves per element; row = 8 elems
    const int s = g_offr[i];
    const int e = s + g_degr[i];
    const int pend16 = s + ((e - s) & ~15);
    int p = s;
    float s0 = 0.f, s1 = 0.f, s2 = 0.f, s3 = 0.f;
    float t0 = 0.f, t1 = 0.f, t2 = 0.f, t3 = 0.f;
    if (p < pend16) {
        uint4 iwa = *(const uint4*)&g_adjr16[p];        // edges 0..7
        uint4 iwb = *(const uint4*)&g_adjr16[p + 8];    // edges 8..15
        while (p < pend16) {
            const int pn = p + 16;
            uint4 iwan = iwa, iwbn = iwb;
            if (pn < pend16) {
                iwan = *(const uint4*)&g_adjr16[pn];
                iwbn = *(const uint4*)&g_adjr16[pn + 8];
            }
            unsigned wa = (quad >= 2) ? iwa.y : iwa.x;
            unsigned wb = (quad >= 2) ? iwa.w : iwa.z;
            unsigned wc = (quad >= 2) ? iwb.y : iwb.x;
            unsigned wd = (quad >= 2) ? iwb.w : iwb.z;
            int ja = (quad & 1) ? (int)(wa >> 16) : (int)(wa & 0xffffu);
            int jb = (quad & 1) ? (int)(wb >> 16) : (int)(wb & 0xffffu);
            int jc = (quad & 1) ? (int)(wc >> 16) : (int)(wc & 0xffffu);
            int jd = (quad & 1) ? (int)(wd >> 16) : (int)(wd & 0xffffu);
            // 4 independent gathers in flight
            uint2 ra = B4[ja * 8 + sub];
            uint2 rb = B4[jb * 8 + sub];
            uint2 rc = B4[jc * 8 + sub];
            uint2 rd = B4[jd * 8 + sub];
            float2 fa01 = __half22float2(*(__half2*)&ra.x);
            float2 fa23 = __half22float2(*(__half2*)&ra.y);
            float2 fb01 = __half22float2(*(__half2*)&rb.x);
            float2 fb23 = __half22float2(*(__half2*)&rb.y);
            float2 fc01 = __half22float2(*(__half2*)&rc.x);
            float2 fc23 = __half22float2(*(__half2*)&rc.y);
            float2 fd01 = __half22float2(*(__half2*)&rd.x);
            float2 fd23 = __half22float2(*(__half2*)&rd.y);
            s0 += fa01.x + fc01.x; s1 += fa01.y + fc01.y;
            s2 += fa23.x + fc23.x; s3 += fa23.y + fc23.y;
            t0 += fb01.x + fd01.x; t1 += fb01.y + fd01.y;
            t2 += fb23.x + fd23.x; t3 += fb23.y + fd23.y;
            iwa = iwan; iwb = iwbn;
            p = pn;
        }
    }
    for (; p + 8 <= e; p += 8) {
        uint4 iw = *(const uint4*)&g_adjr16[p];
        unsigned wa = (quad >= 2) ? iw.y : iw.x;
        unsigned wb = (quad >= 2) ? iw.w : iw.z;
        int ja = (quad & 1) ? (int)(wa >> 16) : (int)(wa & 0xffffu);
        int jb = (quad & 1) ? (int)(wb >> 16) : (int)(wb & 0xffffu);
        uint2 ra = B4[ja * 8 + sub];
        uint2 rb = B4[jb * 8 + sub];
        float2 fa01 = __half22float2(*(__half2*)&ra.x);
        float2 fa23 = __half22float2(*(__half2*)&ra.y);
        float2 fb01 = __half22float2(*(__half2*)&rb.x);
        float2 fb23 = __half22float2(*(__half2*)&rb.y);
        s0 += fa01.x; s1 += fa01.y; s2 += fa23.x; s3 += fa23.y;
        t0 += fb01.x; t1 += fb01.y; t2 += fb23.x; t3 += fb23.y;
    }
    for (; p < e; p += 4) {
        if (p + quad < e) {
            int j = (int)g_adjr16[p + quad];
            uint2 r = B4[j * 8 + sub];
            float2 f01 = __half22float2(*(__half2*)&r.x);
            float2 f23 = __half22float2(*(__half2*)&r.y);
            s0 += f01.x; s1 += f01.y; s2 += f23.x; s3 += f23.y;
        }
    }
    s0 += t0; s1 += t1; s2 += t2; s3 += t3;
    s0 += __shfl_xor_sync(0xffffffffu, s0, 8);  s0 += __shfl_xor_sync(0xffffffffu, s0, 16);
    s1 += __shfl_xor_sync(0xffffffffu, s1, 8);  s1 += __shfl_xor_sync(0xffffffffu, s1, 16);
    s2 += __shfl_xor_sync(0xffffffffu, s2, 8);  s2 += __shfl_xor_sync(0xffffffffu, s2, 16);
    s3 += __shfl_xor_sync(0xffffffffu, s3, 8);  s3 += __shfl_xor_sync(0xffffffffu, s3, 16);
    const float ci = g_cntinv[i];
    float hm0 = s0 * ci, hm1 = s1 * ci, hm2 = s2 * ci, hm3 = s3 * ci;
    float4 h = ((const float4*)g_Bf)[i * 8 + sub];
    float4 w0 = ((const float4*)w_ws)[sub];
    float4 w2 = ((const float4*)(w_ws + HID))[sub];
    float svp = fabsf(h.x - hm0) * w2.x + fabsf(h.y - hm1) * w2.y +
                fabsf(h.z - hm2) * w2.z + fabsf(h.w - hm3) * w2.w;
    float tvp = hm0 * h.x * w0.x + hm1 * h.y * w0.y +
                hm2 * h.z * w0.z + hm3 * h.w * w0.w;
    float sv = warpsum(svp) * 0.25f;   // quads duplicate
    float tv = warpsum(tvp) * 0.25f;
    if (lane == 0) {
        g_S[i] = sv;
        g_T[i] = tv;
    }
}

// ---------------- scalar gather s -> hd ; score ; gate ; fused GEMM -> G ----------------
__global__ void k4_score_gemm(const float* __restrict__ w_ws, const float* __restrict__ W) {
    __shared__ float Wsm[HID * HID];
    const int tid = threadIdx.x;
    const int lane = tid & 31;
    const int i = (blockIdx.x * blockDim.x + tid) >> 5;
    for (int k = tid; k < HID * HID; k += blockDim.x) Wsm[k] = W[k];
    __syncthreads();
    if (i >= NN) return;
    const int s = g_offr[i];
    const int e = s + g_degr[i];
    float sum = 0.f;  // lane-parallel over edges
    for (int p = s + lane; p < e; p += 32) sum += __ldg(&g_S[(int)g_adjr16[p]]);
    float hd = warpsum(sum) * g_cntinv[i];
    float h = g_Bf[i * HID + lane];
    float sc = warpsum(h * w_ws[64 + lane]) + g_T[i] + hd;
    sc = 1.0f / (1.0f + expf(-sc));
    float hnew = (1.0f - sc) * h + sc * g_x0[i * HID + lane];
    // fused next-layer GEMM: G = (hnew @ W) * dinv
    float g = 0.f;
    #pragma unroll
    for (int t = 0; t < HID; t++)
        g = fmaf(__shfl_sync(0xffffffffu, hnew, t), Wsm[t * HID + lane], g);
    g_G[i * HID + lane] = g * g_dinv[i];
}

// ---------------- last block: same but writes A (fp32) for the classifier ----------------
__global__ void k4_score_last(const float* __restrict__ w_ws) {
    const int lane = threadIdx.x & 31;
    const int i = (blockIdx.x * blockDim.x + threadIdx.x) >> 5;
    if (i >= NN) return;
    const int s = g_offr[i];
    const int e = s + g_degr[i];
    float sum = 0.f;
    for (int p = s + lane; p < e; p += 32) sum += __ldg(&g_S[(int)g_adjr16[p]]);
    float hd = warpsum(sum) * g_cntinv[i];
    float h = g_Bf[i * HID + lane];
    float sc = warpsum(h * w_ws[64 + lane]) + g_T[i] + hd;
    sc = 1.0f / (1.0f + expf(-sc));
    g_A[i * HID + lane] = (1.0f - sc) * h + sc * g_x0[i * HID + lane];
}

// ---------------- final classifier GEMM: A@Wl*dinv -> G40 ----------------
__global__ void k1_final(const float* __restrict__ Wl) {
    __shared__ float Wsm[HID * NCLS];
    const int tid = threadIdx.x;
    const int lane = tid & 31;
    const int i = (blockIdx.x * blockDim.x + tid) >> 5;
    for (int k = tid; k < HID * NCLS; k += blockDim.x) Wsm[k] = Wl[k];
    __syncthreads();
    float hv = g_A[i * HID + lane];
    float acc0 = 0.f, acc1 = 0.f;
    #pragma unroll
    for (int t = 0; t < HID; t++) {
        float xv = __shfl_sync(0xffffffffu, hv, t);
        acc0 = fmaf(xv, Wsm[t * NCLS + lane], acc0);
        if (lane < 8) acc1 = fmaf(xv, Wsm[t * NCLS + 32 + lane], acc1);
    }
    float dv = g_dinv[i];
    g_G40[i * NCLS + lane] = acc0 * dv;
    if (lane < 8) g_G40[i * NCLS + 32 + lane] = acc1 * dv;
}

// ---------------- final GCN aggregate -> out ----------------
__global__ void k2_final(const float* __restrict__ bl, float* __restrict__ out) {
    const int lane = threadIdx.x & 31;
    const int i = (blockIdx.x * blockDim.x + threadIdx.x) >> 5;
    if (i >= NN) return;
    float acc0 = g_G40[i * NCLS + lane];
    float acc1 = (lane < 8) ? g_G40[i * NCLS + 32 + lane] : 0.f;
    const int s = g_offc[i];
    const int e = s + g_degc[i];
    for (int p = s; p < e; p++) {
        int idx = (int)g_adjc16[p];
        acc0 += g_G40[idx * NCLS + lane];
        if (lane < 8) acc1 += g_G40[idx * NCLS + 32 + lane];
    }
    float dv = g_dinv[i];
    out[i * NCLS + lane] = dv * acc0 + bl[lane];
    if (lane < 8) out[i * NCLS + 32 + lane] = dv * acc1 + bl[32 + lane];
}

// ---------------- host ----------------
extern "C" void kernel_launch(void* const* d_in, const int* in_sizes, int n_in,
                              void* d_out, int out_size) {
    const float* x    = (const float*)d_in[0];
    const int*   ei   = (const int*)d_in[1];
    const float* W0   = (const float*)d_in[2];
    const float* b0   = (const float*)d_in[3];
    const float* Whh  = (const float*)d_in[4];
    const float* bhh  = (const float*)d_in[5];
    const float* Wl   = (const float*)d_in[6];
    const float* bl   = (const float*)d_in[7];
    const float* lng0 = (const float*)d_in[8];
    const float* lnb0 = (const float*)d_in[9];
    const float* lngm = (const float*)d_in[10];
    const float* lnbm = (const float*)d_in[11];
    const float* w_ws = (const float*)d_in[12];
    const float* Wres = (const float*)d_in[13];
    const float* rg   = (const float*)d_in[14];
    const float* rb   = (const float*)d_in[15];
    float* out = (float*)d_out;

    const int nodeBlocks = (NN + 255) / 256;
    const int warpBlocks = (NN * 32 + 255) / 256;  // warp-per-node, 8 nodes/block

    // CSR build
    zero_deg<<<nodeBlocks, 256>>>();
    hist_edges<<<2048, 256>>>(ei);
    scan_two<<<1, 1024>>>();
    node_init<<<nodeBlocks, 256>>>();
    scatter_edges<<<2048, 256>>>(ei);

    // first layer
    kfirst<<<warpBlocks, 256>>>(x, W0, Wres, rg, rb);

    for (int l = 0; l <= NMID; l++) {  // blocks 0..30
        const float* b   = (l == 0) ? b0   : bhh  + (l - 1) * HID;
        const float* gam = (l == 0) ? lng0 : lngm + (l - 1) * HID;
        const float* bet = (l == 0) ? lnb0 : lnbm + (l - 1) * HID;
        k2_gcn_ln<<<warpBlocks, 256>>>(b, gam, bet);
        k3_mean<<<warpBlocks, 256>>>(w_ws);
        if (l < NMID) {
            k4_score_gemm<<<warpBlocks, 256>>>(w_ws, Whh + l * HID * HID);
        } else {
            k4_score_last<<<warpBlocks, 256>>>(w_ws);
        }
    }
    k1_final<<<warpBlocks, 256>>>(Wl);
    k2_final<<<warpBlocks, 256>>>(bl, out);
}

// round 15
// speedup vs baseline: 1.0455x; 1.0455x over previous
#include <cuda_runtime.h>
#include <cuda_fp16.h>
#include <math.h>

#define NN 50000
#define IN_DIM 256
#define HID 32
#define NCLS 40
#define NEDGE 1600000
#define NMID 30
#define ADJCAP (NEDGE + 8 * NN)   // rows padded to multiples of 8

// ---------------- device scratch (no allocations allowed) ----------------
__device__ int    g_degc[NN], g_degr[NN];
__device__ int    g_offc[NN + 1], g_offr[NN + 1];   // 8-aligned row starts
__device__ int    g_curc[NN], g_curr[NN];
__device__ __align__(16) int g_adjc[ADJCAP];
__device__ __align__(16) int g_adjr[ADJCAP];
__device__ float  g_dinv[NN], g_cntinv[NN];
__device__ float  g_x0[NN * HID];
__device__ __align__(16) float  g_G [NN * HID];   // (h @ W) * dinv — gathered fp32
__device__ __align__(16) float  g_Bf[NN * HID];   // LN(relu(gcn)) — node-local fp32
__device__ __align__(16) __half g_Bh[NN * HID];   // fp16 gather copy (score path)
__device__ float  g_S[NN];           // s[j]=Σ|B-hm|·w2  — scalar gathered fp32
__device__ float  g_T[NN];           // t[i]=Σ hm·h·w0   — node-local scalar
__device__ __half g_G40h[NN * NCLS]; // final (h @ Wl) * dinv — fp16 (one layer only)

__device__ __forceinline__ float warpsum(float v) {
    #pragma unroll
    for (int o = 16; o > 0; o >>= 1) v += __shfl_xor_sync(0xffffffffu, v, o);
    return v;
}

// ---------------- setup: degrees, scans, CSR ----------------
__global__ void zero_deg() {
    for (int i = blockIdx.x * blockDim.x + threadIdx.x; i < NN;
         i += gridDim.x * blockDim.x) {
        g_degc[i] = 0;
        g_degr[i] = 0;
    }
}

__global__ void hist_edges(const int* __restrict__ ei) {
    for (int e = blockIdx.x * blockDim.x + threadIdx.x; e < NEDGE;
         e += gridDim.x * blockDim.x) {
        atomicAdd(&g_degr[ei[e]], 1);          // row
        atomicAdd(&g_degc[ei[NEDGE + e]], 1);  // col
    }
}

// one block, 1024 threads: exclusive scan of BOTH (deg rounded up to 8) arrays per chunk
__global__ void scan_two() {
    __shared__ int wsumc[33], wsumr[33];
    const int tid = threadIdx.x, lane = tid & 31, wid = tid >> 5;
    int runc = 0, runr = 0;
    for (int base = 0; base < NN; base += 1024) {
        int i = base + tid;
        int vc = (i < NN) ? ((g_degc[i] + 7) & ~7) : 0;
        int vr = (i < NN) ? ((g_degr[i] + 7) & ~7) : 0;
        int incc = vc, incr = vr;
        #pragma unroll
        for (int o = 1; o < 32; o <<= 1) {
            int tc = __shfl_up_sync(0xffffffffu, incc, o);
            int tr = __shfl_up_sync(0xffffffffu, incr, o);
            if (lane >= o) { incc += tc; incr += tr; }
        }
        if (lane == 31) { wsumc[wid] = incc; wsumr[wid] = incr; }
        __syncthreads();
        if (wid == 0) {
            int sc = wsumc[lane], sr = wsumr[lane];
            int sic = sc, sir = sr;
            #pragma unroll
            for (int o = 1; o < 32; o <<= 1) {
                int tc = __shfl_up_sync(0xffffffffu, sic, o);
                int tr = __shfl_up_sync(0xffffffffu, sir, o);
                if (lane >= o) { sic += tc; sir += tr; }
            }
            wsumc[lane] = sic - sc;
            wsumr[lane] = sir - sr;
            if (lane == 31) { wsumc[32] = sic; wsumr[32] = sir; }
        }
        __syncthreads();
        if (i < NN) {
            g_offc[i] = runc + wsumc[wid] + incc - vc;
            g_offr[i] = runr + wsumr[wid] + incr - vr;
        }
        runc += wsumc[32];
        runr += wsumr[32];
        __syncthreads();
    }
    if (tid == 0) { g_offc[NN] = runc; g_offr[NN] = runr; }
}

__global__ void node_init() {
    for (int i = blockIdx.x * blockDim.x + threadIdx.x; i < NN;
         i += gridDim.x * blockDim.x) {
        g_curc[i] = g_offc[i];
        g_curr[i] = g_offr[i];
        g_dinv[i] = rsqrtf((float)(g_degc[i] + 1));  // +1 self loop
        g_cntinv[i] = 1.0f / fmaxf((float)g_degr[i], 1.0f);
    }
}

__global__ void scatter_edges(const int* __restrict__ ei) {
    for (int e = blockIdx.x * blockDim.x + threadIdx.x; e < NEDGE;
         e += gridDim.x * blockDim.x) {
        int r = ei[e];
        int c = ei[NEDGE + e];
        int p = atomicAdd(&g_curc[c], 1);
        g_adjc[p] = r;  // CSR by col (gcn target), stores source row
        int q = atomicAdd(&g_curr[r], 1);
        g_adjr[q] = c;  // CSR by row (mean_agg target), stores source col
    }
}

// ---------------- first layer: x@W0*dinv -> G ; LN(relu(x@W_res)) -> x0 ----------------
__global__ void kfirst(const float* __restrict__ x, const float* __restrict__ W0,
                       const float* __restrict__ Wres, const float* __restrict__ rg,
                       const float* __restrict__ rb) {
    __shared__ float Wsm[IN_DIM * HID];  // 32 KB
    const int tid = threadIdx.x;
    const int lane = tid & 31;
    const int i = (blockIdx.x * blockDim.x + tid) >> 5;  // node (grid exact)

    for (int k = tid; k < IN_DIM * HID; k += blockDim.x) Wsm[k] = W0[k];

    float xr[8];
    #pragma unroll
    for (int j = 0; j < 8; j++) xr[j] = x[i * IN_DIM + j * 32 + lane];
    __syncthreads();

    float acc0 = 0.f;
    #pragma unroll
    for (int j = 0; j < 8; j++) {
        #pragma unroll
        for (int t = 0; t < 32; t++) {
            float xv = __shfl_sync(0xffffffffu, xr[j], t);
            acc0 = fmaf(xv, Wsm[(j * 32 + t) * HID + lane], acc0);
        }
    }
    __syncthreads();
    for (int k = tid; k < IN_DIM * HID; k += blockDim.x) Wsm[k] = Wres[k];
    __syncthreads();

    float acc1 = 0.f;
    #pragma unroll
    for (int j = 0; j < 8; j++) {
        #pragma unroll
        for (int t = 0; t < 32; t++) {
            float xv = __shfl_sync(0xffffffffu, xr[j], t);
            acc1 = fmaf(xv, Wsm[(j * 32 + t) * HID + lane], acc1);
        }
    }

    g_G[i * HID + lane] = acc0 * g_dinv[i];

    float r = fmaxf(acc1, 0.f);
    float m = warpsum(r) * (1.f / HID);
    float d = r - m;
    float var = warpsum(d * d) * (1.f / HID);
    g_x0[i * HID + lane] = d * rsqrtf(var + 1e-5f) * rg[lane] + rb[lane];
}

// ---------------- GCN aggregate + bias + relu + LN -> Bf/Bh (dual-edge, 8-wide: R6) ----------------
__global__ void k2_gcn_ln(const float* __restrict__ b, const float* __restrict__ gam,
                          const float* __restrict__ bet) {
    const int lane = threadIdx.x & 31;
    const int sub = lane & 15;     // feature-pair index
    const int half = lane >> 4;    // which edge of the pair
    const int i = (blockIdx.x * blockDim.x + threadIdx.x) >> 5;
    if (i >= NN) return;
    const float2* G2 = (const float2*)g_G;
    const int s = g_offc[i];
    const int e = s + g_degc[i];
    int p = s;
    float2 a0 = {0.f, 0.f}, a1 = {0.f, 0.f}, a2 = {0.f, 0.f}, a3 = {0.f, 0.f};
    for (; p + 8 <= e; p += 8) {
        int4 ia = *(const int4*)&g_adjc[p];
        int4 ib = *(const int4*)&g_adjc[p + 4];
        int j0 = half ? ia.y : ia.x, j1 = half ? ia.w : ia.z;
        int j2 = half ? ib.y : ib.x, j3 = half ? ib.w : ib.z;
        float2 v0 = G2[j0 * 16 + sub];
        float2 v1 = G2[j1 * 16 + sub];
        float2 v2 = G2[j2 * 16 + sub];
        float2 v3 = G2[j3 * 16 + sub];
        a0.x += v0.x; a0.y += v0.y;
        a1.x += v1.x; a1.y += v1.y;
        a2.x += v2.x; a2.y += v2.y;
        a3.x += v3.x; a3.y += v3.y;
    }
    for (; p < e; p += 2) {
        if (p + half < e) {
            int j = g_adjc[p + half];
            float2 v = G2[j * 16 + sub];
            a0.x += v.x; a0.y += v.y;
        }
    }
    float sx = (a0.x + a1.x) + (a2.x + a3.x);
    float sy = (a0.y + a1.y) + (a2.y + a3.y);
    sx += __shfl_xor_sync(0xffffffffu, sx, 16);   // combine halves
    sy += __shfl_xor_sync(0xffffffffu, sy, 16);
    float2 self = G2[i * 16 + sub];               // self loop
    sx += self.x;
    sy += self.y;
    const float dv = g_dinv[i];
    float2 bb = ((const float2*)b)[sub];
    float v0 = fmaxf(fmaf(dv, sx, bb.x), 0.f);
    float v1 = fmaxf(fmaf(dv, sy, bb.y), 0.f);
    // LN over 32 features; lanes duplicate features across halves -> x0.5
    float m = warpsum(v0 + v1) * (0.5f / HID);
    float d0 = v0 - m, d1 = v1 - m;
    float var = warpsum(d0 * d0 + d1 * d1) * (0.5f / HID);
    float rs = rsqrtf(var + 1e-5f);
    float2 gg = ((const float2*)gam)[sub];
    float2 be = ((const float2*)bet)[sub];
    float o0 = d0 * rs * gg.x + be.x;
    float o1 = d1 * rs * gg.y + be.y;
    if (half == 0) {
        ((float2*)g_Bf)[i * 16 + sub] = make_float2(o0, o1);
        ((__half2*)g_Bh)[i * 16 + sub] = __floats2half2_rn(o0, o1);
    }
}

// ---------------- mean_agg(B)->hm ; scalars s,t (dual-edge, 8-wide: R6) ----------------
__global__ void k3_mean(const float* __restrict__ w_ws) {
    const int lane = threadIdx.x & 31;
    const int sub = lane & 15;
    const int half = lane >> 4;
    const int i = (blockIdx.x * blockDim.x + threadIdx.x) >> 5;
    if (i >= NN) return;
    const __half2* B2 = (const __half2*)g_Bh;
    const int s = g_offr[i];
    const int e = s + g_degr[i];
    int p = s;
    float2 a0 = {0.f, 0.f}, a1 = {0.f, 0.f}, a2 = {0.f, 0.f}, a3 = {0.f, 0.f};
    for (; p + 8 <= e; p += 8) {
        int4 ia = *(const int4*)&g_adjr[p];
        int4 ib = *(const int4*)&g_adjr[p + 4];
        int j0 = half ? ia.y : ia.x, j1 = half ? ia.w : ia.z;
        int j2 = half ? ib.y : ib.x, j3 = half ? ib.w : ib.z;
        float2 v0 = __half22float2(B2[j0 * 16 + sub]);
        float2 v1 = __half22float2(B2[j1 * 16 + sub]);
        float2 v2 = __half22float2(B2[j2 * 16 + sub]);
        float2 v3 = __half22float2(B2[j3 * 16 + sub]);
        a0.x += v0.x; a0.y += v0.y;
        a1.x += v1.x; a1.y += v1.y;
        a2.x += v2.x; a2.y += v2.y;
        a3.x += v3.x; a3.y += v3.y;
    }
    for (; p < e; p += 2) {
        if (p + half < e) {
            float2 v = __half22float2(B2[g_adjr[p + half] * 16 + sub]);
            a0.x += v.x; a0.y += v.y;
        }
    }
    float sx = (a0.x + a1.x) + (a2.x + a3.x);
    float sy = (a0.y + a1.y) + (a2.y + a3.y);
    sx += __shfl_xor_sync(0xffffffffu, sx, 16);
    sy += __shfl_xor_sync(0xffffffffu, sy, 16);
    const float ci = g_cntinv[i];
    float hm0 = sx * ci, hm1 = sy * ci;
    float2 h = ((const float2*)g_Bf)[i * 16 + sub];
    float2 w0 = ((const float2*)w_ws)[sub];
    float2 w2 = ((const float2*)(w_ws + HID))[sub];
    float svp = fabsf(h.x - hm0) * w2.x + fabsf(h.y - hm1) * w2.y;
    float tvp = hm0 * h.x * w0.x + hm1 * h.y * w0.y;
    float sv = warpsum(svp) * 0.5f;   // halves duplicate
    float tv = warpsum(tvp) * 0.5f;
    if (lane == 0) {
        g_S[i] = sv;
        g_T[i] = tv;
    }
}

// ---------------- scalar gather s -> hd ; score ; gate ; fused GEMM -> G ----------------
__global__ void k4_score_gemm(const float* __restrict__ w_ws, const float* __restrict__ W) {
    __shared__ float Wsm[HID * HID];
    const int tid = threadIdx.x;
    const int lane = tid & 31;
    const int i = (blockIdx.x * blockDim.x + tid) >> 5;
    for (int k = tid; k < HID * HID; k += blockDim.x) Wsm[k] = W[k];
    __syncthreads();
    if (i >= NN) return;
    const int s = g_offr[i];
    const int e = s + g_degr[i];
    float sum = 0.f;  // lane-parallel over edges
    for (int p = s + lane; p < e; p += 32) sum += __ldg(&g_S[g_adjr[p]]);
    float hd = warpsum(sum) * g_cntinv[i];
    float h = g_Bf[i * HID + lane];
    float sc = warpsum(h * w_ws[64 + lane]) + g_T[i] + hd;
    sc = 1.0f / (1.0f + expf(-sc));
    float hnew = (1.0f - sc) * h + sc * g_x0[i * HID + lane];
    // fused next-layer GEMM: G = (hnew @ W) * dinv
    float g = 0.f;
    #pragma unroll
    for (int t = 0; t < HID; t++)
        g = fmaf(__shfl_sync(0xffffffffu, hnew, t), Wsm[t * HID + lane], g);
    g_G[i * HID + lane] = g * g_dinv[i];
}

// ---------------- last block: score + gate + fused CLASSIFIER GEMM -> G40h (fp16) -------
__global__ void k4_last_gemm(const float* __restrict__ w_ws, const float* __restrict__ Wl) {
    __shared__ float Wsm[HID * NCLS];  // 5 KB
    const int tid = threadIdx.x;
    const int lane = tid & 31;
    const int i = (blockIdx.x * blockDim.x + tid) >> 5;
    for (int k = tid; k < HID * NCLS; k += blockDim.x) Wsm[k] = Wl[k];
    __syncthreads();
    if (i >= NN) return;
    const int s = g_offr[i];
    const int e = s + g_degr[i];
    float sum = 0.f;
    for (int p = s + lane; p < e; p += 32) sum += __ldg(&g_S[g_adjr[p]]);
    float hd = warpsum(sum) * g_cntinv[i];
    float h = g_Bf[i * HID + lane];
    float sc = warpsum(h * w_ws[64 + lane]) + g_T[i] + hd;
    sc = 1.0f / (1.0f + expf(-sc));
    float hnew = (1.0f - sc) * h + sc * g_x0[i * HID + lane];
    // classifier GEMM: G40 = (hnew @ Wl) * dinv, stored fp16 (final layer only)
    float acc0 = 0.f, acc1 = 0.f;
    #pragma unroll
    for (int t = 0; t < HID; t++) {
        float xv = __shfl_sync(0xffffffffu, hnew, t);
        acc0 = fmaf(xv, Wsm[t * NCLS + lane], acc0);
        if (lane < 8) acc1 = fmaf(xv, Wsm[t * NCLS + 32 + lane], acc1);
    }
    float dv = g_dinv[i];
    g_G40h[i * NCLS + lane] = __float2half_rn(acc0 * dv);
    if (lane < 8) g_G40h[i * NCLS + 32 + lane] = __float2half_rn(acc1 * dv);
}

// ---------------- final GCN aggregate (fp16 gather) -> out ----------------
__global__ void k2_final(const float* __restrict__ bl, float* __restrict__ out) {
    const int lane = threadIdx.x & 31;
    const int i = (blockIdx.x * blockDim.x + threadIdx.x) >> 5;
    if (i >= NN) return;
    float acc0 = __half2float(g_G40h[i * NCLS + lane]);
    float acc1 = (lane < 8) ? __half2float(g_G40h[i * NCLS + 32 + lane]) : 0.f;
    const int s = g_offc[i];
    const int e = s + g_degc[i];
    int p = s;
    float b0 = 0.f, b1 = 0.f, b2 = 0.f, b3 = 0.f;
    float c0 = 0.f, c1 = 0.f, c2 = 0.f, c3 = 0.f;
    for (; p + 3 < e; p += 4) {
        int i0 = g_adjc[p], i1 = g_adjc[p + 1], i2 = g_adjc[p + 2], i3 = g_adjc[p + 3];
        b0 += __half2float(g_G40h[i0 * NCLS + lane]);
        b1 += __half2float(g_G40h[i1 * NCLS + lane]);
        b2 += __half2float(g_G40h[i2 * NCLS + lane]);
        b3 += __half2float(g_G40h[i3 * NCLS + lane]);
        if (lane < 8) {
            c0 += __half2float(g_G40h[i0 * NCLS + 32 + lane]);
            c1 += __half2float(g_G40h[i1 * NCLS + 32 + lane]);
            c2 += __half2float(g_G40h[i2 * NCLS + 32 + lane]);
            c3 += __half2float(g_G40h[i3 * NCLS + 32 + lane]);
        }
    }
    for (; p < e; p++) {
        int idx = g_adjc[p];
        acc0 += __half2float(g_G40h[idx * NCLS + lane]);
        if (lane < 8) acc1 += __half2float(g_G40h[idx * NCLS + 32 + lane]);
    }
    acc0 += (b0 + b1) + (b2 + b3);
    acc1 += (c0 + c1) + (c2 + c3);
    float dv = g_dinv[i];
    out[i * NCLS + lane] = dv * acc0 + bl[lane];
    if (lane < 8) out[i * NCLS + 32 + lane] = dv * acc1 + bl[32 + lane];
}

// ---------------- host ----------------
extern "C" void kernel_launch(void* const* d_in, const int* in_sizes, int n_in,
                              void* d_out, int out_size) {
    const float* x    = (const float*)d_in[0];
    const int*   ei   = (const int*)d_in[1];
    const float* W0   = (const float*)d_in[2];
    const float* b0   = (const float*)d_in[3];
    const float* Whh  = (const float*)d_in[4];
    const float* bhh  = (const float*)d_in[5];
    const float* Wl   = (const float*)d_in[6];
    const float* bl   = (const float*)d_in[7];
    const float* lng0 = (const float*)d_in[8];
    const float* lnb0 = (const float*)d_in[9];
    const float* lngm = (const float*)d_in[10];
    const float* lnbm = (const float*)d_in[11];
    const float* w_ws = (const float*)d_in[12];
    const float* Wres = (const float*)d_in[13];
    const float* rg   = (const float*)d_in[14];
    const float* rb   = (const float*)d_in[15];
    float* out = (float*)d_out;

    const int nodeBlocks = (NN + 255) / 256;
    const int warpBlocks = (NN * 32 + 255) / 256;  // warp-per-node, 8 nodes/block

    // CSR build
    zero_deg<<<nodeBlocks, 256>>>();
    hist_edges<<<2048, 256>>>(ei);
    scan_two<<<1, 1024>>>();
    node_init<<<nodeBlocks, 256>>>();
    scatter_edges<<<2048, 256>>>(ei);

    // first layer
    kfirst<<<warpBlocks, 256>>>(x, W0, Wres, rg, rb);

    for (int l = 0; l <= NMID; l++) {  // blocks 0..30
        const float* b   = (l == 0) ? b0   : bhh  + (l - 1) * HID;
        const float* gam = (l == 0) ? lng0 : lngm + (l - 1) * HID;
        const float* bet = (l == 0) ? lnb0 : lnbm + (l - 1) * HID;
        k2_gcn_ln<<<warpBlocks, 256>>>(b, gam, bet);
        k3_mean<<<warpBlocks, 256>>>(w_ws);
        if (l < NMID) {
            k4_score_gemm<<<warpBlocks, 256>>>(w_ws, Whh + l * HID * HID);
        } else {
            k4_last_gemm<<<warpBlocks, 256>>>(w_ws, Wl);
        }
    }
    k2_final<<<warpBlocks, 256>>>(bl, out);
}